// round 1
// baseline (speedup 1.0000x reference)
#include <cuda_runtime.h>
#include <math.h>

#define MAXDISP 192

__global__ __launch_bounds__(256, 8)
void disp_reg_kernel(const float* __restrict__ cost,
                     float* __restrict__ out,
                     int nrows)
{
    const int warp_id = (blockIdx.x * blockDim.x + threadIdx.x) >> 5;
    const int lane    = threadIdx.x & 31;
    if (warp_id >= nrows) return;

    const float* row = cost + (size_t)warp_id * MAXDISP;

    // Each lane loads 6 coalesced strided values; batch the loads up front
    // for MLP, then do the compares.
    float v[6];
#pragma unroll
    for (int k = 0; k < 6; k++) {
        v[k] = row[lane + 32 * k];
    }

    // Local top-2
    float v1 = -INFINITY, v2 = -INFINITY;
    int   i1 = -1,        i2 = -1;
#pragma unroll
    for (int k = 0; k < 6; k++) {
        const int idx = lane + 32 * k;
        if (v[k] > v1) {
            v2 = v1; i2 = i1;
            v1 = v[k]; i1 = idx;
        } else if (v[k] > v2) {
            v2 = v[k]; i2 = idx;
        }
    }

    // Warp-wide top-2 merge (butterfly)
#pragma unroll
    for (int off = 16; off > 0; off >>= 1) {
        const float ov1 = __shfl_xor_sync(0xFFFFFFFFu, v1, off);
        const int   oi1 = __shfl_xor_sync(0xFFFFFFFFu, i1, off);
        const float ov2 = __shfl_xor_sync(0xFFFFFFFFu, v2, off);
        const int   oi2 = __shfl_xor_sync(0xFFFFFFFFu, i2, off);

        if (ov1 > v1) {
            if (v1 > ov2) { v2 = v1;  i2 = i1;  }
            else          { v2 = ov2; i2 = oi2; }
            v1 = ov1; i1 = oi1;
        } else if (ov1 > v2) {
            v2 = ov1; i2 = oi1;
        }
    }

    if (lane == 0) {
        // softmax over {v1, v2} with v1 >= v2: p1 = 1/(1+exp(v2-v1))
        const float p1 = 1.0f / (1.0f + __expf(v2 - v1));
        out[warp_id] = (float)i1 * p1 + (float)i2 * (1.0f - p1);
    }
}

extern "C" void kernel_launch(void* const* d_in, const int* in_sizes, int n_in,
                              void* d_out, int out_size)
{
    const float* cost = (const float*)d_in[0];
    float* out = (float*)d_out;

    const int nrows = in_sizes[0] / MAXDISP;   // 4 * 131072 = 524288

    const int threads = 256;                   // 8 warps/block
    const int warps_per_block = threads / 32;
    const int blocks = (nrows + warps_per_block - 1) / warps_per_block;

    disp_reg_kernel<<<blocks, threads>>>(cost, out, nrows);
}

// round 2
// speedup vs baseline: 1.0454x; 1.0454x over previous
#include <cuda_runtime.h>
#include <math.h>

#define MAXDISP 192

// Monotone map: float bits -> uint32 such that uint compare == float compare.
__device__ __forceinline__ unsigned f2k(float f) {
    unsigned b = __float_as_uint(f);
    return b ^ (unsigned)(((int)b >> 31) | 0x80000000);
}
__device__ __forceinline__ float k2f(unsigned k) {
    unsigned t = (unsigned)((int)k >> 31);         // all-ones if orig positive
    return __uint_as_float(k ^ (~t | 0x80000000u));
}

__global__ __launch_bounds__(256, 8)
void disp_reg_kernel(const float* __restrict__ cost,
                     float* __restrict__ out,
                     int nrows)
{
    const int warp_id = (blockIdx.x * blockDim.x + threadIdx.x) >> 5;
    const int lane    = threadIdx.x & 31;
    if (warp_id >= nrows) return;

    const float* row = cost + (size_t)warp_id * MAXDISP;

    // 3 coalesced 64-bit loads per lane (front-batched for MLP).
    const int b0 = lane * 2;
    const float2 a = *(const float2*)(row + b0);
    const float2 b = *(const float2*)(row + b0 + 64);
    const float2 c = *(const float2*)(row + b0 + 128);

    float x[6] = { a.x, a.y, b.x, b.y, c.x, c.y };
    int  id[6] = { b0, b0 + 1, b0 + 64, b0 + 65, b0 + 128, b0 + 129 };

    // Branchless local top-2 (FSETP + SEL, no branches).
    float v1 = x[0], v2 = -INFINITY;
    int   i1 = id[0], i2 = 0;
#pragma unroll
    for (int k = 1; k < 6; k++) {
        const bool c1 = x[k] > v1;
        const bool c2 = x[k] > v2;
        const float nv2 = c1 ? v1 : (c2 ? x[k] : v2);
        const int   ni2 = c1 ? i1 : (c2 ? id[k] : i2);
        v1 = c1 ? x[k] : v1;
        i1 = c1 ? id[k] : i1;
        v2 = nv2;
        i2 = ni2;
    }

    // Warp top-2 via two hardware reductions on sortable keys.
    const unsigned k1 = f2k(v1);
    const unsigned t1 = __reduce_max_sync(0xFFFFFFFFu, k1);

    const unsigned ball1 = __ballot_sync(0xFFFFFFFFu, k1 == t1);
    const int owner1 = __ffs(ball1) - 1;

    // Owner of top-1 contributes its local second; everyone else their first.
    const unsigned cand   = (lane == owner1) ? f2k(v2) : k1;
    const int      cand_i = (lane == owner1) ? i2 : i1;
    const unsigned t2 = __reduce_max_sync(0xFFFFFFFFu, cand);

    const unsigned ball2 = __ballot_sync(0xFFFFFFFFu, cand == t2);
    const int owner2 = __ffs(ball2) - 1;

    const int top1i = __shfl_sync(0xFFFFFFFFu, i1, owner1);
    const int top2i = __shfl_sync(0xFFFFFFFFu, cand_i, owner2);

    if (lane == 0) {
        const float va = k2f(t1);
        const float vb = k2f(t2);
        // softmax over {va, vb}, va >= vb
        const float p = 1.0f / (1.0f + __expf(vb - va));
        out[warp_id] = (float)top1i * p + (float)top2i * (1.0f - p);
    }
}

extern "C" void kernel_launch(void* const* d_in, const int* in_sizes, int n_in,
                              void* d_out, int out_size)
{
    const float* cost = (const float*)d_in[0];
    float* out = (float*)d_out;

    const int nrows = in_sizes[0] / MAXDISP;   // 4 * 131072 = 524288

    const int threads = 256;                   // 8 warps/block
    const int warps_per_block = threads / 32;
    const int blocks = (nrows + warps_per_block - 1) / warps_per_block;

    disp_reg_kernel<<<blocks, threads>>>(cost, out, nrows);
}

// round 3
// speedup vs baseline: 1.3978x; 1.3370x over previous
#include <cuda_runtime.h>
#include <math.h>

#define MAXDISP 192
#define RPW 4   // rows per warp

// Monotone map: float bits -> uint32 such that uint compare == float compare.
__device__ __forceinline__ unsigned f2k(float f) {
    unsigned b = __float_as_uint(f);
    return b ^ (unsigned)(((int)b >> 31) | 0x80000000);
}
__device__ __forceinline__ float k2f(unsigned k) {
    unsigned t = (unsigned)((int)k >> 31);         // all-ones if orig positive
    return __uint_as_float(k ^ (~t | 0x80000000u));
}

__global__ __launch_bounds__(256, 4)
void disp_reg_kernel(const float* __restrict__ cost,
                     float* __restrict__ out,
                     int nrows)
{
    const int warp = (blockIdx.x * blockDim.x + threadIdx.x) >> 5;
    const int lane = threadIdx.x & 31;
    const int row0 = warp * RPW;
    if (row0 >= nrows) return;

    const float* base = cost + (size_t)row0 * MAXDISP;
    const int b0 = lane * 2;

    // Front-batch all 12 coalesced 64-bit loads (4 rows x 3 vectors) for MLP.
    float2 d[RPW][3];
#pragma unroll
    for (int r = 0; r < RPW; r++) {
#pragma unroll
        for (int k = 0; k < 3; k++) {
            d[r][k] = *(const float2*)(base + r * MAXDISP + b0 + 64 * k);
        }
    }

#pragma unroll
    for (int r = 0; r < RPW; r++) {
        const float x[6]  = { d[r][0].x, d[r][0].y, d[r][1].x,
                              d[r][1].y, d[r][2].x, d[r][2].y };
        const int   id[6] = { b0, b0 + 1, b0 + 64, b0 + 65, b0 + 128, b0 + 129 };

        // Branchless local top-2.
        float v1 = x[0], v2 = -INFINITY;
        int   i1 = id[0], i2 = 0;
#pragma unroll
        for (int k = 1; k < 6; k++) {
            const bool c1 = x[k] > v1;
            const bool c2 = x[k] > v2;
            const float nv2 = c1 ? v1 : (c2 ? x[k] : v2);
            const int   ni2 = c1 ? i1 : (c2 ? id[k] : i2);
            v1 = c1 ? x[k] : v1;
            i1 = c1 ? id[k] : i1;
            v2 = nv2;
            i2 = ni2;
        }

        // Warp top-2 via two hardware reductions on sortable keys.
        const unsigned k1 = f2k(v1);
        const unsigned t1 = __reduce_max_sync(0xFFFFFFFFu, k1);

        const unsigned ball1 = __ballot_sync(0xFFFFFFFFu, k1 == t1);
        const int owner1 = __ffs(ball1) - 1;

        // Only the single owner of top-1 contributes its local second;
        // everyone else their first (keeps exact-tie duplicates correct).
        const unsigned cand   = (lane == owner1) ? f2k(v2) : k1;
        const int      cand_i = (lane == owner1) ? i2 : i1;
        const unsigned t2 = __reduce_max_sync(0xFFFFFFFFu, cand);

        const unsigned ball2 = __ballot_sync(0xFFFFFFFFu, cand == t2);
        const int owner2 = __ffs(ball2) - 1;

        const int top1i = __shfl_sync(0xFFFFFFFFu, i1, owner1);
        const int top2i = __shfl_sync(0xFFFFFFFFu, cand_i, owner2);

        // Lane r finalizes row r -> the 4 exp's run in parallel lanes.
        if (lane == r && (row0 + r) < nrows) {
            const float va = k2f(t1);
            const float vb = k2f(t2);
            const float p = 1.0f / (1.0f + __expf(vb - va));
            out[row0 + r] = (float)top1i * p + (float)top2i * (1.0f - p);
        }
    }
}

extern "C" void kernel_launch(void* const* d_in, const int* in_sizes, int n_in,
                              void* d_out, int out_size)
{
    const float* cost = (const float*)d_in[0];
    float* out = (float*)d_out;

    const int nrows = in_sizes[0] / MAXDISP;   // 4 * 131072 = 524288

    const int threads = 256;                   // 8 warps/block, 32 rows/block
    const int rows_per_block = (threads / 32) * RPW;
    const int blocks = (nrows + rows_per_block - 1) / rows_per_block;

    disp_reg_kernel<<<blocks, threads>>>(cost, out, nrows);
}